// round 14
// baseline (speedup 1.0000x reference)
#include <cuda_runtime.h>
#include <math.h>

#define B 32
#define T 1024
#define NIN 64
#define NRES 2048
#define NOUT 64
#define CAP 320            // max padded nnz per row (mean 204.8, sd 13.6)
#define SCAN_CTAS 128
#define ROWS_PER_CTA 16    // 128 * 16 = 2048, one row per warp (512 thr/CTA)

struct __align__(8) Pair { float w; int k; };

// Static device scratch (sanctioned by harness rules).
__device__ Pair  g_pairs[NRES][CAP];                      // ~5.2 MB
__device__ int   g_cnt[NRES];
__device__ float g_U[(size_t)T * NRES * B];               // 256 MB: [t][n][b]
__device__ float g_S[(size_t)(T + 1) * NRES * B];         // 256 MB: [t][n][b], g_S[0]=0
__device__ unsigned long long g_bar;

// packed f32x2 helpers (FFMA2 — PTX-only on sm_103a, IEEE-exact per lane)
__device__ __forceinline__ void fma2(unsigned long long& a, unsigned long long b,
                                     unsigned long long c) {
    asm("fma.rn.f32x2 %0, %1, %2, %0;" : "+l"(a) : "l"(b), "l"(c));
}
__device__ __forceinline__ unsigned long long dup2(float v) {
    unsigned long long r;
    asm("mov.b64 %0, {%1, %1};" : "=l"(r) : "f"(v));
    return r;
}
__device__ __forceinline__ void unpack2(unsigned long long p, float& lo, float& hi) {
    asm("mov.b64 {%0, %1}, %2;" : "=f"(lo), "=f"(hi) : "l"(p));
}

// ---------------------------------------------------------------------------
// Init: zero h_0 and the barrier counter (runs every launch/replay).
// ---------------------------------------------------------------------------
__global__ void init_kernel() {
    int tid = blockIdx.x * blockDim.x + threadIdx.x;
    if (tid == 0) g_bar = 0ULL;
    for (int i = tid; i < NRES * B; i += gridDim.x * blockDim.x)
        g_S[i] = 0.f;
}

// ---------------------------------------------------------------------------
// Build sparse ELL of W_res: one warp per row, k-ascending deterministic order.
// Pads each row's nnz to a multiple of 16 with zero-weight entries.
// ---------------------------------------------------------------------------
__global__ void build_sparse_kernel(const float* __restrict__ W_res) {
    int warp = threadIdx.x >> 5;
    int lane = threadIdx.x & 31;
    int n = blockIdx.x * 8 + warp;            // grid 256 x 256 threads
    if (n >= NRES) return;
    const float* row = W_res + (size_t)n * NRES;
    int base = 0;
    for (int c = 0; c < NRES; c += 32) {
        float w = row[c + lane];
        unsigned mask = __ballot_sync(0xffffffffu, w != 0.f);
        int pos = base + __popc(mask & ((1u << lane) - 1u));
        if (w != 0.f && pos < CAP) {
            g_pairs[n][pos].w = w;
            g_pairs[n][pos].k = c + lane;
        }
        base += __popc(mask);
    }
    if (lane == 0) {
        int cnt = base < CAP ? base : CAP;
        int cnt16 = (cnt + 15) & ~15;          // pad to multiple of 16
        if (cnt16 > CAP) cnt16 = CAP;
        g_cnt[n] = cnt16;
        for (int j = cnt; j < cnt16; j++) {
            g_pairs[n][j].w = 0.f;
            g_pairs[n][j].k = 0;
        }
    }
}

// ---------------------------------------------------------------------------
// U[t][n][b] = b_res[n] + sum_d x[b][t][d] * W_in[n][d]
// Inner loop in packed f32x2 (4 FFMA2 instead of 8 FFMA per d).
// ---------------------------------------------------------------------------
__global__ __launch_bounds__(256) void u_kernel(const float* __restrict__ x,
                                                const float* __restrict__ W_in,
                                                const float* __restrict__ b_res) {
    __shared__ float s_w[64 * 68];   // [d][n_l], stride 68 (16B-aligned rows)
    __shared__ float s_x[64 * 33];   // [d][b],  stride 33
    int tid = threadIdx.x;
    int n0 = blockIdx.x * 64;
    int t0 = blockIdx.y * 16;

    for (int i = tid; i < 64 * 64; i += 256) {
        int nl = i >> 6, d = i & 63;
        s_w[d * 68 + nl] = W_in[(size_t)(n0 + nl) * NIN + d];
    }

    int warp = tid >> 5, lane = tid & 31;
    float bias[8];
#pragma unroll
    for (int i = 0; i < 8; i++) bias[i] = __ldg(b_res + n0 + warp * 8 + i);

    for (int tt = 0; tt < 16; tt++) {
        int t = t0 + tt;
        __syncthreads();
        for (int i = tid; i < B * 64; i += 256) {
            int b = i >> 6, d = i & 63;
            s_x[d * 33 + b] = x[((size_t)b * T + t) * NIN + d];
        }
        __syncthreads();

        unsigned long long acc2[4] = {0ULL, 0ULL, 0ULL, 0ULL};
#pragma unroll 4
        for (int d = 0; d < 64; d++) {
            unsigned long long xd = dup2(s_x[d * 33 + lane]);
            ulonglong2 wa = *(const ulonglong2*)&s_w[d * 68 + warp * 8];
            ulonglong2 wb = *(const ulonglong2*)&s_w[d * 68 + warp * 8 + 4];
            fma2(acc2[0], wa.x, xd);
            fma2(acc2[1], wa.y, xd);
            fma2(acc2[2], wb.x, xd);
            fma2(acc2[3], wb.y, xd);
        }
        float* out = g_U + ((size_t)t * NRES + n0 + warp * 8) * B + lane;
#pragma unroll
        for (int i = 0; i < 4; i++) {
            float lo, hi;
            unpack2(acc2[i], lo, hi);
            out[(size_t)(2 * i) * B]     = lo + bias[2 * i];
            out[(size_t)(2 * i + 1) * B] = hi + bias[2 * i + 1];
        }
    }
}

// ---------------------------------------------------------------------------
// Persistent scan: 128 CTAs x 512 threads, one row per warp, float4 gather.
// Release/acquire flat-counter grid barrier; next-step U prefetch under the
// wait. (Round-5/12 configuration — best measured across rounds 2-13.)
// ---------------------------------------------------------------------------
__global__ __launch_bounds__(512, 1) void scan_kernel() {
    __shared__ Pair s_pairs[ROWS_PER_CTA][CAP];   // 40 KB
    __shared__ int  s_cnt[ROWS_PER_CTA];
    int tid  = threadIdx.x;
    int warp = tid >> 5;          // 0..15  = row within CTA
    int lane = tid & 31;
    int n0   = blockIdx.x * ROWS_PER_CTA;
    int n    = n0 + warp;

    // each warp stages its own row's (padded) pairs
    {
        int cnt = g_cnt[n];
        if (lane == 0) s_cnt[warp] = cnt;
        for (int j = lane; j < cnt; j += 32)
            s_pairs[warp][j] = g_pairs[n][j];
    }
    __syncthreads();

    const int g  = lane >> 3;        // nnz subgroup 0..3
    const int bq = (lane & 7) * 4;   // batch quad offset
    const Pair* __restrict__ pp = s_pairs[warp];
    const int cnt = s_cnt[warp];

    // prefetch u for t=0 (only lanes with g==0 consume it)
    float4 u = make_float4(0.f, 0.f, 0.f, 0.f);
    if (g == 0) u = *(const float4*)(g_U + (size_t)n * B + bq);

    for (int t = 0; t < T; t++) {
        const float* __restrict__ hp = g_S + (size_t)t * NRES * B;
        float*       __restrict__ hn = g_S + (size_t)(t + 1) * NRES * B;

        float4 acc = make_float4(0.f, 0.f, 0.f, 0.f);
#pragma unroll 4
        for (int j = 0; j < cnt; j += 4) {
            Pair p = pp[j + g];                                  // LDS.64, bcast in group
            float4 h = __ldg((const float4*)(hp + (size_t)p.k * B + bq));
            acc.x = fmaf(p.w, h.x, acc.x);
            acc.y = fmaf(p.w, h.y, acc.y);
            acc.z = fmaf(p.w, h.z, acc.z);
            acc.w = fmaf(p.w, h.w, acc.w);
        }
        // reduce the 4 nnz groups (xor 8, 16)
#pragma unroll
        for (int ofs = 8; ofs <= 16; ofs <<= 1) {
            acc.x += __shfl_xor_sync(0xffffffffu, acc.x, ofs);
            acc.y += __shfl_xor_sync(0xffffffffu, acc.y, ofs);
            acc.z += __shfl_xor_sync(0xffffffffu, acc.z, ofs);
            acc.w += __shfl_xor_sync(0xffffffffu, acc.w, ofs);
        }
        if (g == 0) {
            float4 hv;
            hv.x = tanhf(u.x + acc.x);
            hv.y = tanhf(u.y + acc.y);
            hv.z = tanhf(u.z + acc.z);
            hv.w = tanhf(u.w + acc.w);
            *(float4*)(hn + (size_t)n * B + bq) = hv;
        }

        // ---- grid barrier: syncthreads + release-add, acquire-poll ----
        __syncthreads();                           // all CTA stores done
        if (tid == 0) {
            asm volatile("red.release.gpu.global.add.u64 [%0], %1;"
                         :: "l"(&g_bar), "l"(1ULL) : "memory");
        }
        // prefetch next step's u while we wait (independent of the barrier)
        float4 u_next = make_float4(0.f, 0.f, 0.f, 0.f);
        if (g == 0 && t + 1 < T)
            u_next = *(const float4*)(g_U + ((size_t)(t + 1) * NRES + n) * B + bq);
        if (tid == 0) {
            unsigned long long target = (unsigned long long)(t + 1) * SCAN_CTAS;
            unsigned long long cur;
            do {
                asm volatile("ld.acquire.gpu.global.u64 %0, [%1];"
                             : "=l"(cur) : "l"(&g_bar) : "memory");
            } while (cur < target);
        }
        __syncthreads();                           // broadcast the acquire
        u = u_next;
    }
}

// ---------------------------------------------------------------------------
// y[b][t][o] = b_out[o] + sum_n S[t+1][n][b] * W_out[o][n]
// Both operands staged in smem (round-12 winner); inner loop in packed f32x2.
// ---------------------------------------------------------------------------
__global__ __launch_bounds__(256) void readout_kernel(const float* __restrict__ W_out,
                                                      const float* __restrict__ b_out,
                                                      float* __restrict__ y) {
    __shared__ float s_wo[128 * 68];   // [n_l][o], stride 68 (16B-aligned rows)
    __shared__ float s_s[128 * 32];    // [n_l][b], stride 32 (lane-indexed reads)
    int tid = threadIdx.x, warp = tid >> 5, lane = tid & 31;
    int t = blockIdx.x;

    unsigned long long acc2[4] = {0ULL, 0ULL, 0ULL, 0ULL};

    const float* sp_base = g_S + (size_t)(t + 1) * NRES * B;

    for (int ch = 0; ch < NRES / 128; ch++) {
        __syncthreads();
        for (int i = tid; i < 128 * 64; i += 256) {
            int nl = i & 127, o = i >> 7;
            s_wo[nl * 68 + o] = W_out[(size_t)o * NRES + ch * 128 + nl];
        }
        {
            const float4* src = (const float4*)(sp_base + (size_t)ch * 128 * B);
            float4* dst = (float4*)s_s;
#pragma unroll
            for (int i = 0; i < 4; i++) dst[tid + i * 256] = src[tid + i * 256];
        }
        __syncthreads();
#pragma unroll 4
        for (int nl = 0; nl < 128; nl++) {
            unsigned long long sd = dup2(s_s[nl * 32 + lane]);
            ulonglong2 wa = *(const ulonglong2*)&s_wo[nl * 68 + warp * 8];
            ulonglong2 wb = *(const ulonglong2*)&s_wo[nl * 68 + warp * 8 + 4];
            fma2(acc2[0], wa.x, sd);
            fma2(acc2[1], wa.y, sd);
            fma2(acc2[2], wb.x, sd);
            fma2(acc2[3], wb.y, sd);
        }
    }
#pragma unroll
    for (int i = 0; i < 4; i++) {
        float lo, hi;
        unpack2(acc2[i], lo, hi);
        int o = warp * 8 + 2 * i;
        y[((size_t)lane * T + t) * NOUT + o]     = lo + __ldg(b_out + o);
        y[((size_t)lane * T + t) * NOUT + o + 1] = hi + __ldg(b_out + o + 1);
    }
}

// ---------------------------------------------------------------------------
extern "C" void kernel_launch(void* const* d_in, const int* in_sizes, int n_in,
                              void* d_out, int out_size) {
    const float* x     = (const float*)d_in[0];  // [32,1024,64]
    const float* W_in  = (const float*)d_in[1];  // [2048,64]
    const float* W_res = (const float*)d_in[2];  // [2048,2048]
    const float* b_res = (const float*)d_in[3];  // [2048]
    const float* W_out = (const float*)d_in[4];  // [64,2048]
    const float* b_out = (const float*)d_in[5];  // [64]
    float* y = (float*)d_out;                    // [32,1024,64]

    init_kernel<<<64, 256>>>();
    build_sparse_kernel<<<NRES / 8, 256>>>(W_res);
    dim3 gu(NRES / 64, T / 16);
    u_kernel<<<gu, 256>>>(x, W_in, b_res);
    scan_kernel<<<SCAN_CTAS, 512>>>();
    readout_kernel<<<T, 256>>>(W_out, b_out, y);
}

// round 15
// speedup vs baseline: 1.0921x; 1.0921x over previous
#include <cuda_runtime.h>
#include <math.h>

#define B 32
#define T 1024
#define NIN 64
#define NRES 2048
#define NOUT 64
#define CAP 320            // max padded nnz per row (mean 204.8, sd 13.6)
#define SCAN_CTAS 128
#define ROWS_PER_CTA 16    // 128 * 16 = 2048, one row per warp (512 thr/CTA)
#define T4 4               // timesteps per readout CTA

struct __align__(8) Pair { float w; int k; };

// Static device scratch (sanctioned by harness rules).
__device__ Pair  g_pairs[NRES][CAP];                      // ~5.2 MB
__device__ int   g_cnt[NRES];
__device__ float g_U[(size_t)T * NRES * B];               // 256 MB: [t][n][b]
__device__ float g_S[(size_t)(T + 1) * NRES * B];         // 256 MB: [t][n][b], g_S[0]=0
__device__ unsigned long long g_bar;

// Readout dynamic smem: s_wo 128*68 floats, then 4 S chunks of 128*32 floats.
#define RO_WO_FLOATS (128 * 68)
#define RO_S_FLOATS  (128 * 32)
#define RO_SMEM_BYTES ((RO_WO_FLOATS + T4 * RO_S_FLOATS) * 4)   // 100352 B

// ---------------------------------------------------------------------------
// Init: zero h_0 and the barrier counter (runs every launch/replay).
// ---------------------------------------------------------------------------
__global__ void init_kernel() {
    int tid = blockIdx.x * blockDim.x + threadIdx.x;
    if (tid == 0) g_bar = 0ULL;
    for (int i = tid; i < NRES * B; i += gridDim.x * blockDim.x)
        g_S[i] = 0.f;
}

// ---------------------------------------------------------------------------
// Build sparse ELL of W_res: one warp per row, k-ascending deterministic order.
// Pads each row's nnz to a multiple of 16 with zero-weight entries.
// ---------------------------------------------------------------------------
__global__ void build_sparse_kernel(const float* __restrict__ W_res) {
    int warp = threadIdx.x >> 5;
    int lane = threadIdx.x & 31;
    int n = blockIdx.x * 8 + warp;            // grid 256 x 256 threads
    if (n >= NRES) return;
    const float* row = W_res + (size_t)n * NRES;
    int base = 0;
    for (int c = 0; c < NRES; c += 32) {
        float w = row[c + lane];
        unsigned mask = __ballot_sync(0xffffffffu, w != 0.f);
        int pos = base + __popc(mask & ((1u << lane) - 1u));
        if (w != 0.f && pos < CAP) {
            g_pairs[n][pos].w = w;
            g_pairs[n][pos].k = c + lane;
        }
        base += __popc(mask);
    }
    if (lane == 0) {
        int cnt = base < CAP ? base : CAP;
        int cnt16 = (cnt + 15) & ~15;          // pad to multiple of 16
        if (cnt16 > CAP) cnt16 = CAP;
        g_cnt[n] = cnt16;
        for (int j = cnt; j < cnt16; j++) {
            g_pairs[n][j].w = 0.f;
            g_pairs[n][j].k = 0;
        }
    }
}

// ---------------------------------------------------------------------------
// U[t][n][b] = b_res[n] + sum_d x[b][t][d] * W_in[n][d]   (round-12 version)
// ---------------------------------------------------------------------------
__global__ __launch_bounds__(256) void u_kernel(const float* __restrict__ x,
                                                const float* __restrict__ W_in,
                                                const float* __restrict__ b_res) {
    __shared__ float s_w[64 * 68];   // [d][n_l], stride 68
    __shared__ float s_x[64 * 33];   // [d][b],  stride 33
    int tid = threadIdx.x;
    int n0 = blockIdx.x * 64;
    int t0 = blockIdx.y * 16;

    for (int i = tid; i < 64 * 64; i += 256) {
        int nl = i >> 6, d = i & 63;
        s_w[d * 68 + nl] = W_in[(size_t)(n0 + nl) * NIN + d];
    }

    int warp = tid >> 5, lane = tid & 31;
    float bias[8];
#pragma unroll
    for (int i = 0; i < 8; i++) bias[i] = __ldg(b_res + n0 + warp * 8 + i);

    for (int tt = 0; tt < 16; tt++) {
        int t = t0 + tt;
        __syncthreads();
        for (int i = tid; i < B * 64; i += 256) {
            int b = i >> 6, d = i & 63;
            s_x[d * 33 + b] = x[((size_t)b * T + t) * NIN + d];
        }
        __syncthreads();

        float acc[8];
#pragma unroll
        for (int i = 0; i < 8; i++) acc[i] = 0.f;
#pragma unroll 4
        for (int d = 0; d < 64; d++) {
            float xv = s_x[d * 33 + lane];
            float4 w0 = *(const float4*)&s_w[d * 68 + warp * 8];
            float4 w1 = *(const float4*)&s_w[d * 68 + warp * 8 + 4];
            acc[0] = fmaf(w0.x, xv, acc[0]);
            acc[1] = fmaf(w0.y, xv, acc[1]);
            acc[2] = fmaf(w0.z, xv, acc[2]);
            acc[3] = fmaf(w0.w, xv, acc[3]);
            acc[4] = fmaf(w1.x, xv, acc[4]);
            acc[5] = fmaf(w1.y, xv, acc[5]);
            acc[6] = fmaf(w1.z, xv, acc[6]);
            acc[7] = fmaf(w1.w, xv, acc[7]);
        }
        float* out = g_U + ((size_t)t * NRES + n0 + warp * 8) * B + lane;
#pragma unroll
        for (int i = 0; i < 8; i++) out[(size_t)i * B] = acc[i] + bias[i];
    }
}

// ---------------------------------------------------------------------------
// Persistent scan: 128 CTAs x 512 threads, one row per warp, float4 gather.
// Release/acquire flat-counter grid barrier; next-step U prefetch under the
// wait. (Round-5/12 configuration — best measured across rounds 2-14.)
// ---------------------------------------------------------------------------
__global__ __launch_bounds__(512, 1) void scan_kernel() {
    __shared__ Pair s_pairs[ROWS_PER_CTA][CAP];   // 40 KB
    __shared__ int  s_cnt[ROWS_PER_CTA];
    int tid  = threadIdx.x;
    int warp = tid >> 5;          // 0..15  = row within CTA
    int lane = tid & 31;
    int n0   = blockIdx.x * ROWS_PER_CTA;
    int n    = n0 + warp;

    // each warp stages its own row's (padded) pairs
    {
        int cnt = g_cnt[n];
        if (lane == 0) s_cnt[warp] = cnt;
        for (int j = lane; j < cnt; j += 32)
            s_pairs[warp][j] = g_pairs[n][j];
    }
    __syncthreads();

    const int g  = lane >> 3;        // nnz subgroup 0..3
    const int bq = (lane & 7) * 4;   // batch quad offset
    const Pair* __restrict__ pp = s_pairs[warp];
    const int cnt = s_cnt[warp];

    // prefetch u for t=0 (only lanes with g==0 consume it)
    float4 u = make_float4(0.f, 0.f, 0.f, 0.f);
    if (g == 0) u = *(const float4*)(g_U + (size_t)n * B + bq);

    for (int t = 0; t < T; t++) {
        const float* __restrict__ hp = g_S + (size_t)t * NRES * B;
        float*       __restrict__ hn = g_S + (size_t)(t + 1) * NRES * B;

        float4 acc = make_float4(0.f, 0.f, 0.f, 0.f);
#pragma unroll 4
        for (int j = 0; j < cnt; j += 4) {
            Pair p = pp[j + g];                                  // LDS.64, bcast in group
            float4 h = __ldg((const float4*)(hp + (size_t)p.k * B + bq));
            acc.x = fmaf(p.w, h.x, acc.x);
            acc.y = fmaf(p.w, h.y, acc.y);
            acc.z = fmaf(p.w, h.z, acc.z);
            acc.w = fmaf(p.w, h.w, acc.w);
        }
        // reduce the 4 nnz groups (xor 8, 16)
#pragma unroll
        for (int ofs = 8; ofs <= 16; ofs <<= 1) {
            acc.x += __shfl_xor_sync(0xffffffffu, acc.x, ofs);
            acc.y += __shfl_xor_sync(0xffffffffu, acc.y, ofs);
            acc.z += __shfl_xor_sync(0xffffffffu, acc.z, ofs);
            acc.w += __shfl_xor_sync(0xffffffffu, acc.w, ofs);
        }
        if (g == 0) {
            float4 hv;
            hv.x = tanhf(u.x + acc.x);
            hv.y = tanhf(u.y + acc.y);
            hv.z = tanhf(u.z + acc.z);
            hv.w = tanhf(u.w + acc.w);
            *(float4*)(hn + (size_t)n * B + bq) = hv;
        }

        // ---- grid barrier: syncthreads + release-add, acquire-poll ----
        __syncthreads();                           // all CTA stores done
        if (tid == 0) {
            asm volatile("red.release.gpu.global.add.u64 [%0], %1;"
                         :: "l"(&g_bar), "l"(1ULL) : "memory");
        }
        // prefetch next step's u while we wait (independent of the barrier)
        float4 u_next = make_float4(0.f, 0.f, 0.f, 0.f);
        if (g == 0 && t + 1 < T)
            u_next = *(const float4*)(g_U + ((size_t)(t + 1) * NRES + n) * B + bq);
        if (tid == 0) {
            unsigned long long target = (unsigned long long)(t + 1) * SCAN_CTAS;
            unsigned long long cur;
            do {
                asm volatile("ld.acquire.gpu.global.u64 %0, [%1];"
                             : "=l"(cur) : "l"(&g_bar) : "memory");
            } while (cur < target);
        }
        __syncthreads();                           // broadcast the acquire
        u = u_next;
    }
}

// ---------------------------------------------------------------------------
// y[b][t][o] = b_out[o] + sum_n S[t+1][n][b] * W_out[o][n]
// 4 timesteps per CTA: W_out chunk staged ONCE per chunk and reused across
// 4 t (L2 traffic for W_out cut 4x); all 4 S chunks staged too (R12 winner's
// smem-only inner loop). Dynamic smem ~100 KB, 2 CTAs/SM.
// ---------------------------------------------------------------------------
__global__ __launch_bounds__(256) void readout_kernel(const float* __restrict__ W_out,
                                                      const float* __restrict__ b_out,
                                                      float* __restrict__ y) {
    extern __shared__ float rsm[];
    float* s_wo = rsm;                          // [n_l][o], stride 68
    float* s_s  = rsm + RO_WO_FLOATS;           // [tt][n_l][b], stride 32
    int tid = threadIdx.x, warp = tid >> 5, lane = tid & 31;
    int t0 = blockIdx.x * T4;

    float acc[T4][8];
#pragma unroll
    for (int tt = 0; tt < T4; tt++)
#pragma unroll
        for (int i = 0; i < 8; i++) acc[tt][i] = 0.f;

    for (int ch = 0; ch < NRES / 128; ch++) {
        __syncthreads();
        // stage W_out chunk transposed (once per chunk, reused for 4 t)
        for (int i = tid; i < 128 * 64; i += 256) {
            int nl = i & 127, o = i >> 7;
            s_wo[nl * 68 + o] = W_out[(size_t)o * NRES + ch * 128 + nl];
        }
        // stage 4 S chunks: each 128 rows x 32 b = 1024 float4, coalesced
#pragma unroll
        for (int tt = 0; tt < T4; tt++) {
            const float4* src = (const float4*)(g_S +
                ((size_t)(t0 + tt + 1) * NRES + ch * 128) * B);
            float4* dst = (float4*)(s_s + tt * RO_S_FLOATS);
#pragma unroll
            for (int i = 0; i < 4; i++) dst[tid + i * 256] = src[tid + i * 256];
        }
        __syncthreads();
#pragma unroll 2
        for (int nl = 0; nl < 128; nl++) {
            float4 w0 = *(const float4*)&s_wo[nl * 68 + warp * 8];
            float4 w1 = *(const float4*)&s_wo[nl * 68 + warp * 8 + 4];
#pragma unroll
            for (int tt = 0; tt < T4; tt++) {
                float sv = s_s[tt * RO_S_FLOATS + nl * 32 + lane];
                acc[tt][0] = fmaf(w0.x, sv, acc[tt][0]);
                acc[tt][1] = fmaf(w0.y, sv, acc[tt][1]);
                acc[tt][2] = fmaf(w0.z, sv, acc[tt][2]);
                acc[tt][3] = fmaf(w0.w, sv, acc[tt][3]);
                acc[tt][4] = fmaf(w1.x, sv, acc[tt][4]);
                acc[tt][5] = fmaf(w1.y, sv, acc[tt][5]);
                acc[tt][6] = fmaf(w1.z, sv, acc[tt][6]);
                acc[tt][7] = fmaf(w1.w, sv, acc[tt][7]);
            }
        }
    }
#pragma unroll
    for (int tt = 0; tt < T4; tt++)
#pragma unroll
        for (int i = 0; i < 8; i++) {
            int o = warp * 8 + i;
            y[((size_t)lane * T + t0 + tt) * NOUT + o] = acc[tt][i] + __ldg(b_out + o);
        }
}

// ---------------------------------------------------------------------------
extern "C" void kernel_launch(void* const* d_in, const int* in_sizes, int n_in,
                              void* d_out, int out_size) {
    const float* x     = (const float*)d_in[0];  // [32,1024,64]
    const float* W_in  = (const float*)d_in[1];  // [2048,64]
    const float* W_res = (const float*)d_in[2];  // [2048,2048]
    const float* b_res = (const float*)d_in[3];  // [2048]
    const float* W_out = (const float*)d_in[4];  // [64,2048]
    const float* b_out = (const float*)d_in[5];  // [64]
    float* y = (float*)d_out;                    // [32,1024,64]

    cudaFuncSetAttribute(readout_kernel, cudaFuncAttributeMaxDynamicSharedMemorySize,
                         RO_SMEM_BYTES);

    init_kernel<<<64, 256>>>();
    build_sparse_kernel<<<NRES / 8, 256>>>(W_res);
    dim3 gu(NRES / 64, T / 16);
    u_kernel<<<gu, 256>>>(x, W_in, b_res);
    scan_kernel<<<SCAN_CTAS, 512>>>();
    readout_kernel<<<T / T4, 256, RO_SMEM_BYTES>>>(W_out, b_out, y);
}